// round 1
// baseline (speedup 1.0000x reference)
#include <cuda_runtime.h>
#include <cuda_bf16.h>
#include <math.h>

#define N_NODES   50000
#define N_EDGES   800000
#define HIDDEN    128
#define EDGE_DIM  32
#define NUM_GRAPHS 256

// ---------------- scratch (device globals; no allocations allowed) ----------
__device__ float g_h[N_NODES * HIDDEN];        // node features (25.6 MB)
__device__ float g_agg[N_NODES * HIDDEN];      // message aggregation (25.6 MB); first 150000 floats reused for conv1 agg
__device__ float g_A[N_NODES * 512];           // packed node projections (102.4 MB)
__device__ float g_WW[128 * 512];              // packed weight for node GEMM
__device__ float g_gsum[NUM_GRAPHS * HIDDEN];
__device__ float g_gcnt[NUM_GRAPHS];

// ---------------- conv1: CGConv(C=3, edge=32) -------------------------------
__global__ __launch_bounds__(256) void conv1_kernel(
    const float* __restrict__ x, const int* __restrict__ src, const int* __restrict__ dst,
    const float* __restrict__ eattr,
    const float* __restrict__ Wf, const float* __restrict__ bf,
    const float* __restrict__ Ws, const float* __restrict__ bs,
    float* __restrict__ agg)
{
    __shared__ float wf[38 * 3], ws[38 * 3], bfs[3], bss[3];
    int tid = threadIdx.x;
    if (tid < 114) { wf[tid] = Wf[tid]; ws[tid] = Ws[tid]; }
    if (tid < 3)   { bfs[tid] = bf[tid]; bss[tid] = bs[tid]; }
    __syncthreads();

    int e = blockIdx.x * 256 + tid;
    if (e >= N_EDGES) return;
    int d  = dst[e];
    int sn = src[e];

    float f[3], s[3];
#pragma unroll
    for (int j = 0; j < 3; j++) { f[j] = bfs[j]; s[j] = bss[j]; }

#pragma unroll
    for (int i = 0; i < 3; i++) {
        float xd = x[d * 3 + i];
        float xs = x[sn * 3 + i];
#pragma unroll
        for (int j = 0; j < 3; j++) {
            f[j] += xd * wf[i * 3 + j];
            s[j] += xd * ws[i * 3 + j];
            f[j] += xs * wf[(3 + i) * 3 + j];
            s[j] += xs * ws[(3 + i) * 3 + j];
        }
    }
    const float4* ep = (const float4*)(eattr + (size_t)e * 32);
#pragma unroll
    for (int q = 0; q < 8; q++) {
        float4 v = ep[q];
        float ev[4] = {v.x, v.y, v.z, v.w};
#pragma unroll
        for (int r = 0; r < 4; r++) {
            int k = 6 + q * 4 + r;
#pragma unroll
            for (int j = 0; j < 3; j++) {
                f[j] += ev[r] * wf[k * 3 + j];
                s[j] += ev[r] * ws[k * 3 + j];
            }
        }
    }
#pragma unroll
    for (int j = 0; j < 3; j++) {
        float sg = 1.f / (1.f + __expf(-f[j]));
        float sp = fmaxf(s[j], 0.f) + log1pf(__expf(-fabsf(s[j])));
        atomicAdd(agg + (size_t)d * 3 + j, sg * sp);
    }
}

// ---------------- node projection: h = relu((x+agg1) @ Wp + bp) -------------
__global__ __launch_bounds__(256) void proj_kernel(
    const float* __restrict__ x, const float* __restrict__ agg1,
    const float* __restrict__ Wp, const float* __restrict__ bp,
    float* __restrict__ h)
{
    int idx = blockIdx.x * 256 + threadIdx.x;
    if (idx >= N_NODES * HIDDEN) return;
    int n = idx >> 7, c = idx & 127;
    float v = bp[c];
#pragma unroll
    for (int i = 0; i < 3; i++)
        v += (x[n * 3 + i] + agg1[n * 3 + i]) * Wp[i * 128 + c];
    h[idx] = fmaxf(v, 0.f);
}

// ---------------- pack WW: column j -> (role=j>>8, c=(j&255)>>1, gate=j&1) ---
__global__ __launch_bounds__(256) void pack_kernel(
    const float* __restrict__ Wf, const float* __restrict__ Ws, float* __restrict__ WW)
{
    int idx = blockIdx.x * 256 + threadIdx.x;   // 128*512
    if (idx >= 128 * 512) return;
    int k = idx >> 9;
    int j = idx & 511;
    int role = j >> 8;
    int c = (j & 255) >> 1;
    int gate = j & 1;
    const float* G = gate ? Ws : Wf;
    WW[idx] = G[(role * 128 + k) * 128 + c];
}

// ---------------- node GEMM: A[50000,512] = h[50000,128] @ WW[128,512] ------
__global__ __launch_bounds__(256) void gemm_node(
    const float* __restrict__ H, const float* __restrict__ W, float* __restrict__ A)
{
    __shared__ float hs[16][132];   // transposed tile: hs[k][m]
    __shared__ float ws[16][128];
    int bm = blockIdx.x * 128;
    int bn = blockIdx.y * 128;
    int tid = threadIdx.x;
    int tm = (tid >> 4) * 8;
    int tn = (tid & 15) * 8;
    float acc[8][8];
#pragma unroll
    for (int i = 0; i < 8; i++)
#pragma unroll
        for (int j = 0; j < 8; j++) acc[i][j] = 0.f;

    for (int k0 = 0; k0 < 128; k0 += 16) {
#pragma unroll
        for (int t = 0; t < 2; t++) {
            int li = tid + t * 256;           // 0..511 float4 loads
            int m  = li >> 2;
            int kq = li & 3;
            int row = bm + m; if (row >= N_NODES) row = N_NODES - 1;
            float4 v = *(const float4*)(H + (size_t)row * 128 + k0 + kq * 4);
            hs[kq * 4 + 0][m] = v.x;
            hs[kq * 4 + 1][m] = v.y;
            hs[kq * 4 + 2][m] = v.z;
            hs[kq * 4 + 3][m] = v.w;
        }
#pragma unroll
        for (int t = 0; t < 2; t++) {
            int li = tid + t * 256;
            int k  = li >> 5;
            int cq = li & 31;
            float4 v = *(const float4*)(W + (size_t)(k0 + k) * 512 + bn + cq * 4);
            *(float4*)&ws[k][cq * 4] = v;
        }
        __syncthreads();
#pragma unroll
        for (int k = 0; k < 16; k++) {
            float4 a0 = *(float4*)&hs[k][tm];
            float4 a1 = *(float4*)&hs[k][tm + 4];
            float4 w0 = *(float4*)&ws[k][tn];
            float4 w1 = *(float4*)&ws[k][tn + 4];
            float am[8] = {a0.x, a0.y, a0.z, a0.w, a1.x, a1.y, a1.z, a1.w};
            float wn[8] = {w0.x, w0.y, w0.z, w0.w, w1.x, w1.y, w1.z, w1.w};
#pragma unroll
            for (int i = 0; i < 8; i++)
#pragma unroll
                for (int j = 0; j < 8; j++)
                    acc[i][j] += am[i] * wn[j];
        }
        __syncthreads();
    }
#pragma unroll
    for (int i = 0; i < 8; i++) {
        int row = bm + tm + i;
        if (row < N_NODES) {
            float4 o0 = {acc[i][0], acc[i][1], acc[i][2], acc[i][3]};
            float4 o1 = {acc[i][4], acc[i][5], acc[i][6], acc[i][7]};
            *(float4*)(A + (size_t)row * 512 + bn + tn)     = o0;
            *(float4*)(A + (size_t)row * 512 + bn + tn + 4) = o1;
        }
    }
}

// ---------------- big CGConv edge kernel -------------------------------------
#define EPB 256
__global__ __launch_bounds__(256, 2) void edge_kernel(
    const int* __restrict__ src, const int* __restrict__ dst,
    const float* __restrict__ eattr,
    const float* __restrict__ Wf, const float* __restrict__ Ws,   // [288,128] layer slices
    const float* __restrict__ bf, const float* __restrict__ bs,
    const float* __restrict__ A, float* __restrict__ agg)
{
    int tid = threadIdx.x;
    int c   = tid & 127;
    int grp = tid >> 7;

    float wf[32], wsr[32];
#pragma unroll
    for (int k = 0; k < 32; k++) {
        wf[k]  = Wf[(256 + k) * 128 + c];
        wsr[k] = Ws[(256 + k) * 128 + c];
    }
    float bfc = bf[c], bsc = bs[c];

    int ebase = blockIdx.x * EPB;
    for (int i = grp; i < EPB; i += 2) {
        int e = ebase + i;
        if (e >= N_EDGES) break;
        int d  = dst[e];
        int sn = src[e];
        float2 ad = *(const float2*)(A + (size_t)d  * 512 + 2 * c);
        float2 as = *(const float2*)(A + (size_t)sn * 512 + 256 + 2 * c);
        const float4* ep = (const float4*)(eattr + (size_t)e * 32);

        float f0 = 0.f, f1 = 0.f, s0 = 0.f, s1 = 0.f;
#pragma unroll
        for (int q = 0; q < 8; q += 2) {
            float4 v = ep[q];
            f0 += v.x * wf[q * 4 + 0];  s0 += v.x * wsr[q * 4 + 0];
            f0 += v.y * wf[q * 4 + 1];  s0 += v.y * wsr[q * 4 + 1];
            f0 += v.z * wf[q * 4 + 2];  s0 += v.z * wsr[q * 4 + 2];
            f0 += v.w * wf[q * 4 + 3];  s0 += v.w * wsr[q * 4 + 3];
            float4 u = ep[q + 1];
            f1 += u.x * wf[q * 4 + 4];  s1 += u.x * wsr[q * 4 + 4];
            f1 += u.y * wf[q * 4 + 5];  s1 += u.y * wsr[q * 4 + 5];
            f1 += u.z * wf[q * 4 + 6];  s1 += u.z * wsr[q * 4 + 6];
            f1 += u.w * wf[q * 4 + 7];  s1 += u.w * wsr[q * 4 + 7];
        }
        float f = bfc + ad.x + as.x + f0 + f1;
        float s = bsc + ad.y + as.y + s0 + s1;
        float sg = 1.f / (1.f + __expf(-f));
        float sp = fmaxf(s, 0.f) + log1pf(__expf(-fabsf(s)));
        atomicAdd(agg + (size_t)d * 128 + c, sg * sp);
    }
}

// ---------------- h = relu(h + agg) ------------------------------------------
__global__ __launch_bounds__(256) void relu_add_kernel(float* __restrict__ h, const float* __restrict__ agg)
{
    int idx = blockIdx.x * 256 + threadIdx.x;
    if (idx >= N_NODES * HIDDEN) return;
    h[idx] = fmaxf(h[idx] + agg[idx], 0.f);
}

// ---------------- global mean pool (sums + counts via atomics) ---------------
__global__ __launch_bounds__(256) void pool_kernel(
    const float* __restrict__ h, const int* __restrict__ batch,
    float* __restrict__ gsum, float* __restrict__ gcnt)
{
    int idx = blockIdx.x * 256 + threadIdx.x;
    if (idx >= N_NODES * HIDDEN) return;
    int n = idx >> 7, c = idx & 127;
    int b = batch[n];
    atomicAdd(gsum + (size_t)b * 128 + c, h[idx]);
    if (c == 0) atomicAdd(gcnt + b, 1.f);
}

// ---------------- final MLP: g = relu(mean@W1+b1); out = g@Wh^T + bh ---------
__global__ __launch_bounds__(128) void final_kernel(
    const float* __restrict__ gsum, const float* __restrict__ gcnt,
    const float* __restrict__ W1, const float* __restrict__ b1,
    const float* __restrict__ Wh, const float* __restrict__ bh,
    float* __restrict__ out)
{
    __shared__ float mean[128];
    __shared__ float ga[128];
    int g = blockIdx.x;
    int c = threadIdx.x;
    float cnt = fmaxf(gcnt[g], 1.f);
    mean[c] = gsum[(size_t)g * 128 + c] / cnt;
    __syncthreads();
    float acc = b1[c];
#pragma unroll 8
    for (int k = 0; k < 128; k++)
        acc += mean[k] * W1[k * 128 + c];
    ga[c] = fmaxf(acc, 0.f);
    __syncthreads();
    if (c < 5) {
        float o = bh[c];
#pragma unroll 8
        for (int k = 0; k < 128; k++)
            o += ga[k] * Wh[c * 128 + k];
        out[g * 5 + c] = o;
    }
}

// =============================================================================
extern "C" void kernel_launch(void* const* d_in, const int* in_sizes, int n_in,
                              void* d_out, int out_size)
{
    const float* x        = (const float*)d_in[0];
    const int*   eidx     = (const int*)  d_in[1];
    const float* eattr    = (const float*)d_in[2];
    const int*   batch    = (const int*)  d_in[3];
    const float* Wf1      = (const float*)d_in[4];
    const float* bf1      = (const float*)d_in[5];
    const float* Ws1      = (const float*)d_in[6];
    const float* bs1      = (const float*)d_in[7];
    const float* Wp       = (const float*)d_in[8];
    const float* bp       = (const float*)d_in[9];
    const float* Wf_convs = (const float*)d_in[10];
    const float* bf_convs = (const float*)d_in[11];
    const float* Ws_convs = (const float*)d_in[12];
    const float* bs_convs = (const float*)d_in[13];
    const float* W1       = (const float*)d_in[14];
    const float* b1       = (const float*)d_in[15];
    const float* Wh       = (const float*)d_in[16];
    const float* bh       = (const float*)d_in[17];
    float* out = (float*)d_out;

    const int* srcp = eidx;
    const int* dstp = eidx + N_EDGES;

    float *p_h, *p_agg, *p_A, *p_WW, *p_gsum, *p_gcnt;
    cudaGetSymbolAddress((void**)&p_h,    g_h);
    cudaGetSymbolAddress((void**)&p_agg,  g_agg);
    cudaGetSymbolAddress((void**)&p_A,    g_A);
    cudaGetSymbolAddress((void**)&p_WW,   g_WW);
    cudaGetSymbolAddress((void**)&p_gsum, g_gsum);
    cudaGetSymbolAddress((void**)&p_gcnt, g_gcnt);

    const int EB = (N_EDGES + 255) / 256;             // 3125
    const int NB = (N_NODES * HIDDEN + 255) / 256;

    // conv1
    cudaMemsetAsync(p_agg, 0, (size_t)N_NODES * 3 * sizeof(float));
    conv1_kernel<<<EB, 256>>>(x, srcp, dstp, eattr, Wf1, bf1, Ws1, bs1, p_agg);
    proj_kernel<<<NB, 256>>>(x, p_agg, Wp, bp, p_h);

    // two big CGConv layers
    for (int l = 0; l < 2; l++) {
        const float* Wf = Wf_convs + (size_t)l * 288 * 128;
        const float* Ws = Ws_convs + (size_t)l * 288 * 128;
        const float* bf = bf_convs + (size_t)l * 128;
        const float* bs = bs_convs + (size_t)l * 128;

        pack_kernel<<<(128 * 512 + 255) / 256, 256>>>(Wf, Ws, p_WW);
        dim3 gg((N_NODES + 127) / 128, 4);
        gemm_node<<<gg, 256>>>(p_h, p_WW, p_A);
        cudaMemsetAsync(p_agg, 0, (size_t)N_NODES * HIDDEN * sizeof(float));
        edge_kernel<<<EB, 256>>>(srcp, dstp, eattr, Wf, Ws, bf, bs, p_A, p_agg);
        relu_add_kernel<<<NB, 256>>>(p_h, p_agg);
    }

    // pooling + head MLP
    cudaMemsetAsync(p_gsum, 0, (size_t)NUM_GRAPHS * HIDDEN * sizeof(float));
    cudaMemsetAsync(p_gcnt, 0, (size_t)NUM_GRAPHS * sizeof(float));
    pool_kernel<<<NB, 256>>>(p_h, batch, p_gsum, p_gcnt);
    final_kernel<<<NUM_GRAPHS, 128>>>(p_gsum, p_gcnt, W1, b1, Wh, bh, out);
}

// round 2
// speedup vs baseline: 1.3113x; 1.3113x over previous
#include <cuda_runtime.h>
#include <cuda_fp16.h>
#include <math.h>

#define N_NODES   50000
#define N_EDGES   800000
#define HIDDEN    128
#define EDGE_DIM  32
#define NUM_GRAPHS 256

// ---------------- scratch (device globals) ----------------------------------
__device__ float  g_h[N_NODES * HIDDEN];
__device__ float  g_agg[N_NODES * HIDDEN];
__device__ __half g_A[N_NODES * 512];          // packed projections, fp16 (51 MB)
__device__ float  g_WW[128 * 512];
__device__ float  g_gsum[NUM_GRAPHS * HIDDEN];
__device__ float  g_gcnt[NUM_GRAPHS];

// ---------------- f32x2 helpers ----------------------------------------------
__device__ __forceinline__ unsigned long long mk2(float lo, float hi) {
    unsigned long long r; asm("mov.b64 %0, {%1, %2};" : "=l"(r) : "f"(lo), "f"(hi)); return r;
}
__device__ __forceinline__ unsigned long long dup2(float x) {
    unsigned long long r; asm("mov.b64 %0, {%1, %1};" : "=l"(r) : "f"(x)); return r;
}
__device__ __forceinline__ void fma2(unsigned long long &d, unsigned long long a, unsigned long long b) {
    asm("fma.rn.f32x2 %0, %1, %2, %3;" : "=l"(d) : "l"(a), "l"(b), "l"(d));
}
__device__ __forceinline__ float2 unpk(unsigned long long v) {
    float2 r; asm("mov.b64 {%0, %1}, %2;" : "=f"(r.x), "=f"(r.y) : "l"(v)); return r;
}

// ---------------- conv1: CGConv(C=3, edge=32) -------------------------------
__global__ __launch_bounds__(256) void conv1_kernel(
    const float* __restrict__ x, const int* __restrict__ src, const int* __restrict__ dst,
    const float* __restrict__ eattr,
    const float* __restrict__ Wf, const float* __restrict__ bf,
    const float* __restrict__ Ws, const float* __restrict__ bs,
    float* __restrict__ agg)
{
    __shared__ float wf[38 * 3], ws[38 * 3], bfs[3], bss[3];
    int tid = threadIdx.x;
    if (tid < 114) { wf[tid] = Wf[tid]; ws[tid] = Ws[tid]; }
    if (tid < 3)   { bfs[tid] = bf[tid]; bss[tid] = bs[tid]; }
    __syncthreads();

    int e = blockIdx.x * 256 + tid;
    int d  = dst[e];
    int sn = src[e];

    float f[3], s[3];
#pragma unroll
    for (int j = 0; j < 3; j++) { f[j] = bfs[j]; s[j] = bss[j]; }

#pragma unroll
    for (int i = 0; i < 3; i++) {
        float xd = x[d * 3 + i];
        float xs = x[sn * 3 + i];
#pragma unroll
        for (int j = 0; j < 3; j++) {
            f[j] += xd * wf[i * 3 + j];
            s[j] += xd * ws[i * 3 + j];
            f[j] += xs * wf[(3 + i) * 3 + j];
            s[j] += xs * ws[(3 + i) * 3 + j];
        }
    }
    const float4* ep = (const float4*)(eattr + (size_t)e * 32);
#pragma unroll
    for (int q = 0; q < 8; q++) {
        float4 v = ep[q];
        float ev[4] = {v.x, v.y, v.z, v.w};
#pragma unroll
        for (int r = 0; r < 4; r++) {
            int k = 6 + q * 4 + r;
#pragma unroll
            for (int j = 0; j < 3; j++) {
                f[j] += ev[r] * wf[k * 3 + j];
                s[j] += ev[r] * ws[k * 3 + j];
            }
        }
    }
#pragma unroll
    for (int j = 0; j < 3; j++) {
        float sg = __fdividef(1.f, 1.f + __expf(-f[j]));
        float sp = fmaxf(s[j], 0.f) + __logf(1.f + __expf(-fabsf(s[j])));
        atomicAdd(agg + (size_t)d * 3 + j, sg * sp);
    }
}

// ---------------- node projection -------------------------------------------
__global__ __launch_bounds__(256) void proj_kernel(
    const float* __restrict__ x, const float* __restrict__ agg1,
    const float* __restrict__ Wp, const float* __restrict__ bp,
    float* __restrict__ h)
{
    int idx = blockIdx.x * 256 + threadIdx.x;
    int n = idx >> 7, c = idx & 127;
    float v = bp[c];
#pragma unroll
    for (int i = 0; i < 3; i++)
        v += (x[n * 3 + i] + agg1[n * 3 + i]) * Wp[i * 128 + c];
    h[idx] = fmaxf(v, 0.f);
}

// ---------------- pack WW ----------------------------------------------------
__global__ __launch_bounds__(256) void pack_kernel(
    const float* __restrict__ Wf, const float* __restrict__ Ws, float* __restrict__ WW)
{
    int idx = blockIdx.x * 256 + threadIdx.x;   // 128*512
    int k = idx >> 9;
    int j = idx & 511;
    int role = j >> 8;
    int c = (j & 255) >> 1;
    int gate = j & 1;
    const float* G = gate ? Ws : Wf;
    WW[idx] = G[(role * 128 + k) * 128 + c];
}

// ---------------- node GEMM: A[50000,512](fp16) = h @ WW --------------------
__global__ __launch_bounds__(256) void gemm_node(
    const float* __restrict__ H, const float* __restrict__ W, __half* __restrict__ A)
{
    __shared__ float hs[16][132];
    __shared__ float ws[16][128];
    int bm = blockIdx.x * 128;
    int bn = blockIdx.y * 128;
    int tid = threadIdx.x;
    int tm = (tid >> 4) * 8;
    int tn = (tid & 15) * 8;
    unsigned long long acc2[8][4];
#pragma unroll
    for (int i = 0; i < 8; i++)
#pragma unroll
        for (int j = 0; j < 4; j++) acc2[i][j] = 0ULL;

    for (int k0 = 0; k0 < 128; k0 += 16) {
#pragma unroll
        for (int t = 0; t < 2; t++) {
            int li = tid + t * 256;
            int m  = li >> 2;
            int kq = li & 3;
            int row = bm + m; if (row >= N_NODES) row = N_NODES - 1;
            float4 v = *(const float4*)(H + (size_t)row * 128 + k0 + kq * 4);
            hs[kq * 4 + 0][m] = v.x;
            hs[kq * 4 + 1][m] = v.y;
            hs[kq * 4 + 2][m] = v.z;
            hs[kq * 4 + 3][m] = v.w;
        }
#pragma unroll
        for (int t = 0; t < 2; t++) {
            int li = tid + t * 256;
            int k  = li >> 5;
            int cq = li & 31;
            float4 v = *(const float4*)(W + (size_t)(k0 + k) * 512 + bn + cq * 4);
            *(float4*)&ws[k][cq * 4] = v;
        }
        __syncthreads();
#pragma unroll
        for (int k = 0; k < 16; k++) {
            float4 a0 = *(float4*)&hs[k][tm];
            float4 a1 = *(float4*)&hs[k][tm + 4];
            float4 w0 = *(float4*)&ws[k][tn];
            float4 w1 = *(float4*)&ws[k][tn + 4];
            unsigned long long wp0 = mk2(w0.x, w0.y);
            unsigned long long wp1 = mk2(w0.z, w0.w);
            unsigned long long wp2 = mk2(w1.x, w1.y);
            unsigned long long wp3 = mk2(w1.z, w1.w);
            float am[8] = {a0.x, a0.y, a0.z, a0.w, a1.x, a1.y, a1.z, a1.w};
#pragma unroll
            for (int i = 0; i < 8; i++) {
                unsigned long long ad = dup2(am[i]);
                fma2(acc2[i][0], ad, wp0);
                fma2(acc2[i][1], ad, wp1);
                fma2(acc2[i][2], ad, wp2);
                fma2(acc2[i][3], ad, wp3);
            }
        }
        __syncthreads();
    }
#pragma unroll
    for (int i = 0; i < 8; i++) {
        int row = bm + tm + i;
        if (row < N_NODES) {
            uint4 o;
            unsigned* op = (unsigned*)&o;
#pragma unroll
            for (int p = 0; p < 4; p++) {
                float2 fp = unpk(acc2[i][p]);
                __half2 hp = __floats2half2_rn(fp.x, fp.y);
                op[p] = *(unsigned*)&hp;
            }
            *(uint4*)(A + (size_t)row * 512 + bn + tn) = o;
        }
    }
}

// ---------------- big CGConv edge kernel -------------------------------------
__global__ __launch_bounds__(256, 2) void edge_kernel(
    const int* __restrict__ src, const int* __restrict__ dst,
    const float* __restrict__ eattr,
    const float* __restrict__ Wf, const float* __restrict__ Ws,
    const float* __restrict__ bf, const float* __restrict__ bs,
    const __half2* __restrict__ A2, float* __restrict__ agg)
{
    int tid = threadIdx.x;
    int c   = tid & 127;
    int grp = tid >> 7;

    unsigned long long wf2[16], ws2[16];
#pragma unroll
    for (int t = 0; t < 16; t++) {
        wf2[t] = mk2(Wf[(256 + 2 * t) * 128 + c], Wf[(257 + 2 * t) * 128 + c]);
        ws2[t] = mk2(Ws[(256 + 2 * t) * 128 + c], Ws[(257 + 2 * t) * 128 + c]);
    }
    float bfc = bf[c], bsc = bs[c];

    int ebase = blockIdx.x * 256 + grp * 128;
#pragma unroll 2
    for (int t = 0; t < 128; t++) {
        int e  = ebase + t;
        int d  = dst[e];
        int sn = src[e];
        __half2 vd = A2[(size_t)d  * 256 + c];
        __half2 vs = A2[(size_t)sn * 256 + 128 + c];
        const float4* ep = (const float4*)(eattr + (size_t)e * 32);

        unsigned long long af = 0ULL, as_ = 0ULL;
#pragma unroll
        for (int q = 0; q < 8; q++) {
            float4 v = ep[q];
            unsigned long long e0 = mk2(v.x, v.y);
            unsigned long long e1 = mk2(v.z, v.w);
            fma2(af,  e0, wf2[2 * q]);
            fma2(af,  e1, wf2[2 * q + 1]);
            fma2(as_, e0, ws2[2 * q]);
            fma2(as_, e1, ws2[2 * q + 1]);
        }
        float2 F = unpk(af), S = unpk(as_);
        float2 fd = __half22float2(vd);
        float2 fv = __half22float2(vs);
        float f = bfc + fd.x + fv.x + F.x + F.y;
        float s = bsc + fd.y + fv.y + S.x + S.y;
        float sg = __fdividef(1.f, 1.f + __expf(-f));
        float sp = fmaxf(s, 0.f) + __logf(1.f + __expf(-fabsf(s)));
        atomicAdd(agg + (size_t)d * 128 + c, sg * sp);
    }
}

// ---------------- h = relu(h + agg) ------------------------------------------
__global__ __launch_bounds__(256) void relu_add_kernel(float* __restrict__ h, const float* __restrict__ agg)
{
    int idx = blockIdx.x * 256 + threadIdx.x;
    h[idx] = fmaxf(h[idx] + agg[idx], 0.f);
}

// ---------------- final relu + mean pool fused --------------------------------
__global__ __launch_bounds__(256) void relu_pool_kernel(
    const float* __restrict__ h, const float* __restrict__ agg,
    const int* __restrict__ batch,
    float* __restrict__ gsum, float* __restrict__ gcnt)
{
    int idx = blockIdx.x * 256 + threadIdx.x;
    int n = idx >> 7, c = idx & 127;
    float v = fmaxf(h[idx] + agg[idx], 0.f);
    int b = batch[n];
    atomicAdd(gsum + (size_t)b * 128 + c, v);
    if (c == 0) atomicAdd(gcnt + b, 1.f);
}

// ---------------- final MLP ---------------------------------------------------
__global__ __launch_bounds__(128) void final_kernel(
    const float* __restrict__ gsum, const float* __restrict__ gcnt,
    const float* __restrict__ W1, const float* __restrict__ b1,
    const float* __restrict__ Wh, const float* __restrict__ bh,
    float* __restrict__ out)
{
    __shared__ float mean[128];
    __shared__ float ga[128];
    int g = blockIdx.x;
    int c = threadIdx.x;
    float cnt = fmaxf(gcnt[g], 1.f);
    mean[c] = gsum[(size_t)g * 128 + c] / cnt;
    __syncthreads();
    float acc = b1[c];
#pragma unroll 8
    for (int k = 0; k < 128; k++)
        acc += mean[k] * W1[k * 128 + c];
    ga[c] = fmaxf(acc, 0.f);
    __syncthreads();
    if (c < 5) {
        float o = bh[c];
#pragma unroll 8
        for (int k = 0; k < 128; k++)
            o += ga[k] * Wh[c * 128 + k];
        out[g * 5 + c] = o;
    }
}

// =============================================================================
extern "C" void kernel_launch(void* const* d_in, const int* in_sizes, int n_in,
                              void* d_out, int out_size)
{
    const float* x        = (const float*)d_in[0];
    const int*   eidx     = (const int*)  d_in[1];
    const float* eattr    = (const float*)d_in[2];
    const int*   batch    = (const int*)  d_in[3];
    const float* Wf1      = (const float*)d_in[4];
    const float* bf1      = (const float*)d_in[5];
    const float* Ws1      = (const float*)d_in[6];
    const float* bs1      = (const float*)d_in[7];
    const float* Wp       = (const float*)d_in[8];
    const float* bp       = (const float*)d_in[9];
    const float* Wf_convs = (const float*)d_in[10];
    const float* bf_convs = (const float*)d_in[11];
    const float* Ws_convs = (const float*)d_in[12];
    const float* bs_convs = (const float*)d_in[13];
    const float* W1       = (const float*)d_in[14];
    const float* b1       = (const float*)d_in[15];
    const float* Wh       = (const float*)d_in[16];
    const float* bh       = (const float*)d_in[17];
    float* out = (float*)d_out;

    const int* srcp = eidx;
    const int* dstp = eidx + N_EDGES;

    float *p_h, *p_agg, *p_WW, *p_gsum, *p_gcnt;
    __half *p_A;
    cudaGetSymbolAddress((void**)&p_h,    g_h);
    cudaGetSymbolAddress((void**)&p_agg,  g_agg);
    cudaGetSymbolAddress((void**)&p_A,    g_A);
    cudaGetSymbolAddress((void**)&p_WW,   g_WW);
    cudaGetSymbolAddress((void**)&p_gsum, g_gsum);
    cudaGetSymbolAddress((void**)&p_gcnt, g_gcnt);

    const int EB = N_EDGES / 256;                     // 3125 exact
    const int NB = (N_NODES * HIDDEN) / 256;          // 25000 exact

    // conv1
    cudaMemsetAsync(p_agg, 0, (size_t)N_NODES * 3 * sizeof(float));
    conv1_kernel<<<EB, 256>>>(x, srcp, dstp, eattr, Wf1, bf1, Ws1, bs1, p_agg);
    proj_kernel<<<NB, 256>>>(x, p_agg, Wp, bp, p_h);

    cudaMemsetAsync(p_gsum, 0, (size_t)NUM_GRAPHS * HIDDEN * sizeof(float));
    cudaMemsetAsync(p_gcnt, 0, (size_t)NUM_GRAPHS * sizeof(float));

    // two big CGConv layers
    for (int l = 0; l < 2; l++) {
        const float* Wf = Wf_convs + (size_t)l * 288 * 128;
        const float* Ws = Ws_convs + (size_t)l * 288 * 128;
        const float* bf = bf_convs + (size_t)l * 128;
        const float* bs = bs_convs + (size_t)l * 128;

        pack_kernel<<<(128 * 512) / 256, 256>>>(Wf, Ws, p_WW);
        dim3 gg((N_NODES + 127) / 128, 4);
        gemm_node<<<gg, 256>>>(p_h, p_WW, p_A);
        cudaMemsetAsync(p_agg, 0, (size_t)N_NODES * HIDDEN * sizeof(float));
        edge_kernel<<<EB, 256>>>(srcp, dstp, eattr, Wf, Ws, bf, bs, (const __half2*)p_A, p_agg);
        if (l == 0)
            relu_add_kernel<<<NB, 256>>>(p_h, p_agg);
        else
            relu_pool_kernel<<<NB, 256>>>(p_h, p_agg, batch, p_gsum, p_gcnt);
    }

    final_kernel<<<NUM_GRAPHS, 128>>>(p_gsum, p_gcnt, W1, b1, Wh, bh, out);
}

// round 3
// speedup vs baseline: 2.0686x; 1.5775x over previous
#include <cuda_runtime.h>
#include <cuda_fp16.h>
#include <math.h>

#define N_NODES   50000
#define N_EDGES   800000
#define HIDDEN    128
#define EDGE_DIM  32
#define NUM_GRAPHS 256
#define PF 4

// ---------------- scratch (device globals) ----------------------------------
__device__ float  g_h[N_NODES * HIDDEN];
__device__ float  g_agg[N_NODES * HIDDEN];
__device__ __half g_A[N_NODES * 512];          // packed projections, fp16 (51 MB)
__device__ float  g_WW[128 * 512];
__device__ float  g_gsum[NUM_GRAPHS * HIDDEN];
__device__ float  g_gcnt[NUM_GRAPHS];

// ---------------- f32x2 helpers ----------------------------------------------
__device__ __forceinline__ unsigned long long mk2(float lo, float hi) {
    unsigned long long r; asm("mov.b64 %0, {%1, %2};" : "=l"(r) : "f"(lo), "f"(hi)); return r;
}
__device__ __forceinline__ unsigned long long dup2(float x) {
    unsigned long long r; asm("mov.b64 %0, {%1, %1};" : "=l"(r) : "f"(x)); return r;
}
__device__ __forceinline__ void fma2(unsigned long long &d, unsigned long long a, unsigned long long b) {
    asm("fma.rn.f32x2 %0, %1, %2, %3;" : "=l"(d) : "l"(a), "l"(b), "l"(d));
}
__device__ __forceinline__ float2 unpk(unsigned long long v) {
    float2 r; asm("mov.b64 {%0, %1}, %2;" : "=f"(r.x), "=f"(r.y) : "l"(v)); return r;
}

// ---------------- conv1: CGConv(C=3, edge=32) -------------------------------
__global__ __launch_bounds__(256) void conv1_kernel(
    const float* __restrict__ x, const int* __restrict__ src, const int* __restrict__ dst,
    const float* __restrict__ eattr,
    const float* __restrict__ Wf, const float* __restrict__ bf,
    const float* __restrict__ Ws, const float* __restrict__ bs,
    float* __restrict__ agg)
{
    __shared__ float wf[38 * 3], ws[38 * 3], bfs[3], bss[3];
    int tid = threadIdx.x;
    if (tid < 114) { wf[tid] = Wf[tid]; ws[tid] = Ws[tid]; }
    if (tid < 3)   { bfs[tid] = bf[tid]; bss[tid] = bs[tid]; }
    __syncthreads();

    int e = blockIdx.x * 256 + tid;
    int d  = dst[e];
    int sn = src[e];

    float f[3], s[3];
#pragma unroll
    for (int j = 0; j < 3; j++) { f[j] = bfs[j]; s[j] = bss[j]; }

#pragma unroll
    for (int i = 0; i < 3; i++) {
        float xd = x[d * 3 + i];
        float xs = x[sn * 3 + i];
#pragma unroll
        for (int j = 0; j < 3; j++) {
            f[j] += xd * wf[i * 3 + j];
            s[j] += xd * ws[i * 3 + j];
            f[j] += xs * wf[(3 + i) * 3 + j];
            s[j] += xs * ws[(3 + i) * 3 + j];
        }
    }
    const float4* ep = (const float4*)(eattr + (size_t)e * 32);
#pragma unroll
    for (int q = 0; q < 8; q++) {
        float4 v = ep[q];
        float ev[4] = {v.x, v.y, v.z, v.w};
#pragma unroll
        for (int r = 0; r < 4; r++) {
            int k = 6 + q * 4 + r;
#pragma unroll
            for (int j = 0; j < 3; j++) {
                f[j] += ev[r] * wf[k * 3 + j];
                s[j] += ev[r] * ws[k * 3 + j];
            }
        }
    }
#pragma unroll
    for (int j = 0; j < 3; j++) {
        float sg = __fdividef(1.f, 1.f + __expf(-f[j]));
        float sp = fmaxf(s[j], 0.f) + __logf(1.f + __expf(-fabsf(s[j])));
        atomicAdd(agg + (size_t)d * 3 + j, sg * sp);
    }
}

// ---------------- node projection -------------------------------------------
__global__ __launch_bounds__(256) void proj_kernel(
    const float* __restrict__ x, const float* __restrict__ agg1,
    const float* __restrict__ Wp, const float* __restrict__ bp,
    float* __restrict__ h)
{
    int idx = blockIdx.x * 256 + threadIdx.x;
    int n = idx >> 7, c = idx & 127;
    float v = bp[c];
#pragma unroll
    for (int i = 0; i < 3; i++)
        v += (x[n * 3 + i] + agg1[n * 3 + i]) * Wp[i * 128 + c];
    h[idx] = fmaxf(v, 0.f);
}

// ---------------- pack WW ----------------------------------------------------
__global__ __launch_bounds__(256) void pack_kernel(
    const float* __restrict__ Wf, const float* __restrict__ Ws, float* __restrict__ WW)
{
    int idx = blockIdx.x * 256 + threadIdx.x;   // 128*512
    int k = idx >> 9;
    int j = idx & 511;
    int role = j >> 8;
    int c = (j & 255) >> 1;
    int gate = j & 1;
    const float* G = gate ? Ws : Wf;
    WW[idx] = G[(role * 128 + k) * 128 + c];
}

// ---------------- node GEMM: A[50000,512](fp16) = h @ WW --------------------
__global__ __launch_bounds__(256) void gemm_node(
    const float* __restrict__ H, const float* __restrict__ W, __half* __restrict__ A)
{
    __shared__ float hs[16][132];
    __shared__ float ws[16][128];
    int bm = blockIdx.x * 128;
    int bn = blockIdx.y * 128;
    int tid = threadIdx.x;
    int tm = (tid >> 4) * 8;
    int tn = (tid & 15) * 8;
    unsigned long long acc2[8][4];
#pragma unroll
    for (int i = 0; i < 8; i++)
#pragma unroll
        for (int j = 0; j < 4; j++) acc2[i][j] = 0ULL;

    for (int k0 = 0; k0 < 128; k0 += 16) {
#pragma unroll
        for (int t = 0; t < 2; t++) {
            int li = tid + t * 256;
            int m  = li >> 2;
            int kq = li & 3;
            int row = bm + m; if (row >= N_NODES) row = N_NODES - 1;
            float4 v = *(const float4*)(H + (size_t)row * 128 + k0 + kq * 4);
            hs[kq * 4 + 0][m] = v.x;
            hs[kq * 4 + 1][m] = v.y;
            hs[kq * 4 + 2][m] = v.z;
            hs[kq * 4 + 3][m] = v.w;
        }
#pragma unroll
        for (int t = 0; t < 2; t++) {
            int li = tid + t * 256;
            int k  = li >> 5;
            int cq = li & 31;
            float4 v = *(const float4*)(W + (size_t)(k0 + k) * 512 + bn + cq * 4);
            *(float4*)&ws[k][cq * 4] = v;
        }
        __syncthreads();
#pragma unroll
        for (int k = 0; k < 16; k++) {
            float4 a0 = *(float4*)&hs[k][tm];
            float4 a1 = *(float4*)&hs[k][tm + 4];
            float4 w0 = *(float4*)&ws[k][tn];
            float4 w1 = *(float4*)&ws[k][tn + 4];
            unsigned long long wp0 = mk2(w0.x, w0.y);
            unsigned long long wp1 = mk2(w0.z, w0.w);
            unsigned long long wp2 = mk2(w1.x, w1.y);
            unsigned long long wp3 = mk2(w1.z, w1.w);
            float am[8] = {a0.x, a0.y, a0.z, a0.w, a1.x, a1.y, a1.z, a1.w};
#pragma unroll
            for (int i = 0; i < 8; i++) {
                unsigned long long ad = dup2(am[i]);
                fma2(acc2[i][0], ad, wp0);
                fma2(acc2[i][1], ad, wp1);
                fma2(acc2[i][2], ad, wp2);
                fma2(acc2[i][3], ad, wp3);
            }
        }
        __syncthreads();
    }
#pragma unroll
    for (int i = 0; i < 8; i++) {
        int row = bm + tm + i;
        if (row < N_NODES) {
            uint4 o;
            unsigned* op = (unsigned*)&o;
#pragma unroll
            for (int p = 0; p < 4; p++) {
                float2 fp = unpk(acc2[i][p]);
                __half2 hp = __floats2half2_rn(fp.x, fp.y);
                op[p] = *(unsigned*)&hp;
            }
            *(uint4*)(A + (size_t)row * 512 + bn + tn) = o;
        }
    }
}

// ---------------- big CGConv edge kernel (smem-staged, pipelined) ------------
__global__ __launch_bounds__(256, 2) void edge_kernel(
    const int* __restrict__ src, const int* __restrict__ dst,
    const float* __restrict__ eattr,
    const float* __restrict__ Wf, const float* __restrict__ Ws,
    const float* __restrict__ bf, const float* __restrict__ bs,
    const __half2* __restrict__ A2, float* __restrict__ agg)
{
    __shared__ float es[2][128][36];      // padded edge-attr tile (36 KB)
    __shared__ int2  di[2][128];          // (dst, src) per edge

    int tid = threadIdx.x;
    int grp = tid >> 7;
    int c   = tid & 127;

    // per-channel weights for the edge slice, packed over k as f32x2
    unsigned long long wf2[16], ws2[16];
#pragma unroll
    for (int t = 0; t < 16; t++) {
        wf2[t] = mk2(__ldg(&Wf[(256 + 2 * t) * 128 + c]), __ldg(&Wf[(257 + 2 * t) * 128 + c]));
        ws2[t] = mk2(__ldg(&Ws[(256 + 2 * t) * 128 + c]), __ldg(&Ws[(257 + 2 * t) * 128 + c]));
    }
    float bfc = __ldg(&bf[c]), bsc = __ldg(&bs[c]);

    int ebase = blockIdx.x * 256 + grp * 128;

    // stage indices
    {
        int e = ebase + c;
        di[grp][c] = make_int2(dst[e], src[e]);
    }
    // stage edge attrs (streaming, evict-first)
    {
        const float4* base4 = (const float4*)(eattr + (size_t)ebase * 32);
#pragma unroll
        for (int r = 0; r < 8; r++) {
            int li = c + 128 * r;          // 0..1023
            int ei = li >> 3;
            int k4 = li & 7;
            float4 v = __ldcs(base4 + li);
            *(float4*)&es[grp][ei][k4 * 4] = v;
        }
    }
    __syncthreads();

    // prime gather pipeline
    __half2 pvd[PF], pvs[PF];
#pragma unroll
    for (int i = 0; i < PF; i++) {
        int2 ds = di[grp][i];
        pvd[i] = __ldg(A2 + (size_t)ds.x * 256 + c);
        pvs[i] = __ldg(A2 + (size_t)ds.y * 256 + 128 + c);
    }

#pragma unroll 4
    for (int i = 0; i < 128; i++) {
        __half2 vd = pvd[i & (PF - 1)];
        __half2 vs = pvs[i & (PF - 1)];
        if (i + PF < 128) {
            int2 ds = di[grp][i + PF];
            pvd[i & (PF - 1)] = __ldg(A2 + (size_t)ds.x * 256 + c);
            pvs[i & (PF - 1)] = __ldg(A2 + (size_t)ds.y * 256 + 128 + c);
        }

        const float* ep = es[grp][i];
        unsigned long long af = 0ULL, as_ = 0ULL;
#pragma unroll
        for (int q = 0; q < 16; q++) {
            unsigned long long ev = *(const unsigned long long*)(ep + 2 * q);
            fma2(af,  ev, wf2[q]);
            fma2(as_, ev, ws2[q]);
        }
        float2 F = unpk(af), S = unpk(as_);
        float2 fd = __half22float2(vd);
        float2 fv = __half22float2(vs);
        float f = bfc + fd.x + fv.x + F.x + F.y;
        float s = bsc + fd.y + fv.y + S.x + S.y;
        float sg = __fdividef(1.f, 1.f + __expf(-f));
        float sp = fmaxf(s, 0.f) + __logf(1.f + __expf(-fabsf(s)));
        int d = di[grp][i].x;
        atomicAdd(agg + (size_t)d * 128 + c, sg * sp);
    }
}

// ---------------- h = relu(h + agg) ------------------------------------------
__global__ __launch_bounds__(256) void relu_add_kernel(float* __restrict__ h, const float* __restrict__ agg)
{
    int idx = blockIdx.x * 256 + threadIdx.x;
    h[idx] = fmaxf(h[idx] + agg[idx], 0.f);
}

// ---------------- final relu + mean pool fused --------------------------------
__global__ __launch_bounds__(256) void relu_pool_kernel(
    const float* __restrict__ h, const float* __restrict__ agg,
    const int* __restrict__ batch,
    float* __restrict__ gsum, float* __restrict__ gcnt)
{
    int idx = blockIdx.x * 256 + threadIdx.x;
    int n = idx >> 7, c = idx & 127;
    float v = fmaxf(h[idx] + agg[idx], 0.f);
    int b = batch[n];
    atomicAdd(gsum + (size_t)b * 128 + c, v);
    if (c == 0) atomicAdd(gcnt + b, 1.f);
}

// ---------------- final MLP ---------------------------------------------------
__global__ __launch_bounds__(128) void final_kernel(
    const float* __restrict__ gsum, const float* __restrict__ gcnt,
    const float* __restrict__ W1, const float* __restrict__ b1,
    const float* __restrict__ Wh, const float* __restrict__ bh,
    float* __restrict__ out)
{
    __shared__ float mean[128];
    __shared__ float ga[128];
    int g = blockIdx.x;
    int c = threadIdx.x;
    float cnt = fmaxf(gcnt[g], 1.f);
    mean[c] = gsum[(size_t)g * 128 + c] / cnt;
    __syncthreads();
    float acc = b1[c];
#pragma unroll 8
    for (int k = 0; k < 128; k++)
        acc += mean[k] * W1[k * 128 + c];
    ga[c] = fmaxf(acc, 0.f);
    __syncthreads();
    if (c < 5) {
        float o = bh[c];
#pragma unroll 8
        for (int k = 0; k < 128; k++)
            o += ga[k] * Wh[c * 128 + k];
        out[g * 5 + c] = o;
    }
}

// =============================================================================
extern "C" void kernel_launch(void* const* d_in, const int* in_sizes, int n_in,
                              void* d_out, int out_size)
{
    const float* x        = (const float*)d_in[0];
    const int*   eidx     = (const int*)  d_in[1];
    const float* eattr    = (const float*)d_in[2];
    const int*   batch    = (const int*)  d_in[3];
    const float* Wf1      = (const float*)d_in[4];
    const float* bf1      = (const float*)d_in[5];
    const float* Ws1      = (const float*)d_in[6];
    const float* bs1      = (const float*)d_in[7];
    const float* Wp       = (const float*)d_in[8];
    const float* bp       = (const float*)d_in[9];
    const float* Wf_convs = (const float*)d_in[10];
    const float* bf_convs = (const float*)d_in[11];
    const float* Ws_convs = (const float*)d_in[12];
    const float* bs_convs = (const float*)d_in[13];
    const float* W1       = (const float*)d_in[14];
    const float* b1       = (const float*)d_in[15];
    const float* Wh       = (const float*)d_in[16];
    const float* bh       = (const float*)d_in[17];
    float* out = (float*)d_out;

    const int* srcp = eidx;
    const int* dstp = eidx + N_EDGES;

    float *p_h, *p_agg, *p_WW, *p_gsum, *p_gcnt;
    __half *p_A;
    cudaGetSymbolAddress((void**)&p_h,    g_h);
    cudaGetSymbolAddress((void**)&p_agg,  g_agg);
    cudaGetSymbolAddress((void**)&p_A,    g_A);
    cudaGetSymbolAddress((void**)&p_WW,   g_WW);
    cudaGetSymbolAddress((void**)&p_gsum, g_gsum);
    cudaGetSymbolAddress((void**)&p_gcnt, g_gcnt);

    const int EB = N_EDGES / 256;                     // 3125 exact
    const int NB = (N_NODES * HIDDEN) / 256;          // 25000 exact

    // conv1
    cudaMemsetAsync(p_agg, 0, (size_t)N_NODES * 3 * sizeof(float));
    conv1_kernel<<<EB, 256>>>(x, srcp, dstp, eattr, Wf1, bf1, Ws1, bs1, p_agg);
    proj_kernel<<<NB, 256>>>(x, p_agg, Wp, bp, p_h);

    cudaMemsetAsync(p_gsum, 0, (size_t)NUM_GRAPHS * HIDDEN * sizeof(float));
    cudaMemsetAsync(p_gcnt, 0, (size_t)NUM_GRAPHS * sizeof(float));

    // two big CGConv layers
    for (int l = 0; l < 2; l++) {
        const float* Wf = Wf_convs + (size_t)l * 288 * 128;
        const float* Ws = Ws_convs + (size_t)l * 288 * 128;
        const float* bf = bf_convs + (size_t)l * 128;
        const float* bs = bs_convs + (size_t)l * 128;

        pack_kernel<<<(128 * 512) / 256, 256>>>(Wf, Ws, p_WW);
        dim3 gg((N_NODES + 127) / 128, 4);
        gemm_node<<<gg, 256>>>(p_h, p_WW, p_A);
        cudaMemsetAsync(p_agg, 0, (size_t)N_NODES * HIDDEN * sizeof(float));
        edge_kernel<<<EB, 256>>>(srcp, dstp, eattr, Wf, Ws, bf, bs, (const __half2*)p_A, p_agg);
        if (l == 0)
            relu_add_kernel<<<NB, 256>>>(p_h, p_agg);
        else
            relu_pool_kernel<<<NB, 256>>>(p_h, p_agg, batch, p_gsum, p_gcnt);
    }

    final_kernel<<<NUM_GRAPHS, 128>>>(p_gsum, p_gcnt, W1, b1, Wh, bh, out);
}